// round 15
// baseline (speedup 1.0000x reference)
#include <cuda_runtime.h>
#include <cuda_fp16.h>
#include <math.h>
#include <stdint.h>

// Problem constants
#define BB 8
#define NN 4096
#define CC 640
#define SS 77
#define XD 768
#define HH 8
#define DH 80
#define BETA 0.5f
#define TAU 0.1f
#define EPSI 1e-8f

// ---------------- scratch (no cudaMalloc allowed) ----------------
__device__ __half g_Xh[BB * NN * CC];      // X, fp16
__device__ __half g_Qh[BB * NN * CC];      // Q, fp16
__device__ __half g_attnh[BB * NN * CC];   // attention out, fp16
__device__ __half g_Eh[BB * SS * XD];      // E, fp16
__device__ __half g_Kh[BB * SS * CC];      // K, fp16
__device__ float g_V[BB * SS * CC];
__device__ __half g_Vth[BB * CC * 80];     // CORA-erased V, fp16, [b][d][s] (pads stay 0)
__device__ float g_uhat[SS * CC];
__device__ float g_ahat[SS * CC];
__device__ float g_G[SS * 3];
__device__ __half g_Wh[4][XD * CC];        // transposed fp16 weights [n][k]

// ---------------- block reduce helper ----------------
__device__ __forceinline__ float blockSum(float v, float* red) {
    #pragma unroll
    for (int o = 16; o; o >>= 1) v += __shfl_xor_sync(0xffffffffu, v, o);
    int w = threadIdx.x >> 5, l = threadIdx.x & 31;
    __syncthreads();
    if (l == 0) red[w] = v;
    __syncthreads();
    if (w == 0) {
        float x = (l < (int)(blockDim.x >> 5)) ? red[l] : 0.0f;
        #pragma unroll
        for (int o = 4; o; o >>= 1) x += __shfl_xor_sync(0xffffffffu, x, o);
        if (l == 0) red[0] = x;
    }
    __syncthreads();
    return red[0];
}

// ---------------- fp32 -> fp16 bulk convert (n % 8 == 0) ----------------
__global__ __launch_bounds__(256) void to_half8(
    const float* __restrict__ src, __half* __restrict__ dst, int n)
{
    int i = (blockIdx.x * 256 + threadIdx.x) * 8;
    if (i >= n) return;
    float4 a = *(const float4*)(src + i);
    float4 b = *(const float4*)(src + i + 4);
    __half2 h[4];
    h[0] = __floats2half2_rn(a.x, a.y);
    h[1] = __floats2half2_rn(a.z, a.w);
    h[2] = __floats2half2_rn(b.x, b.y);
    h[3] = __floats2half2_rn(b.z, b.w);
    *(uint4*)(dst + i) = *(uint4*)h;
}

// ---------------- fused weight transpose + fp16: Wh[z][n][k] ----------------
__global__ __launch_bounds__(256) void transpose_all(
    const float* __restrict__ Wq, const float* __restrict__ Wk,
    const float* __restrict__ Wv, const float* __restrict__ Wo,
    __half* __restrict__ Wh)
{
    __shared__ float t[32][33];
    const int z = blockIdx.z;
    const float* W = (z == 0) ? Wq : (z == 1) ? Wk : (z == 2) ? Wv : Wo;
    const int K = (z == 1 || z == 2) ? XD : CC;
    __half* Wt = Wh + (size_t)z * (XD * CC);

    const int k0 = blockIdx.y * 32, n0 = blockIdx.x * 32;
    if (k0 >= K) return;
    const int tx = threadIdx.x & 31, ty = threadIdx.x >> 5;
    #pragma unroll
    for (int i = ty; i < 32; i += 8) {
        int k = k0 + i, n = n0 + tx;
        if (k < K) t[i][tx] = W[(size_t)k * CC + n];
    }
    __syncthreads();
    #pragma unroll
    for (int i = ty; i < 32; i += 8) {
        int n = n0 + i, k = k0 + tx;
        if (k < K)
            Wt[(size_t)n * K + k] = __float2half_rn(t[tx][i]);
    }
}

// =====================================================================
// FP16 tensor-core GEMM v6 (proven R12): k64 stages, 3-stage cp.async,
// ldmatrix, 2 CTAs/SM, dual-B, runtime out dtype.
// =====================================================================
#define HSTR6 72
#define A6_BUF (128 * HSTR6)
#define B6_BUF (128 * HSTR6)
#define ST6_BUF (A6_BUF + B6_BUF)
#define GV6_SMEM (3 * ST6_BUF * 2)   // 110592 B

__global__ __launch_bounds__(256, 2) void gemm_v6(
    const __half* __restrict__ A,
    const __half* __restrict__ B1, const float* __restrict__ bias,
    void* __restrict__ C1, int outh1,
    const __half* __restrict__ B2, void* __restrict__ C2, int outh2,
    int nsplit, int M, int K)
{
    extern __shared__ __half sh[];
    const int tid = threadIdx.x;
    int bx = blockIdx.x;
    const __half* Bt = B1;
    void* Cp = C1;
    int outh = outh1;
    const float* bp = bias;
    if (B2 != nullptr && bx >= nsplit) { Bt = B2; Cp = C2; outh = outh2; bp = nullptr; bx -= nsplit; }

    const int wid = tid >> 5, lane = tid & 31;
    const int wm = wid >> 2, wn = wid & 3;
    const int g = lane >> 2, tg = lane & 3;
    const int row0 = blockIdx.y * 128, col0 = bx * 128;

    const unsigned smem_base = (unsigned)__cvta_generic_to_shared(sh);
    const int mi = lane >> 3;
    const int mr = lane & 7;

    float acc[4][4][4];
    #pragma unroll
    for (int i = 0; i < 4; i++)
        #pragma unroll
        for (int j = 0; j < 4; j++)
            #pragma unroll
            for (int r = 0; r < 4; r++) acc[i][j][r] = 0.0f;

    const int KT = K / 64;

    auto issue = [&](int tile, int stage) {
        const unsigned sb = smem_base + stage * ST6_BUF * 2;
        #pragma unroll
        for (int j = 0; j < 4; j++) {
            int idx = tid + j * 256;
            int r = idx >> 3;
            int c = (idx & 7) * 8;
            int gr = row0 + r;
            int sz = (gr < M) ? 16 : 0;
            const __half* src = A + (size_t)(gr < M ? gr : (M - 1)) * K + tile * 64 + c;
            unsigned dst = sb + (r * HSTR6 + c) * 2;
            asm volatile("cp.async.cg.shared.global [%0], [%1], 16, %2;"
                         :: "r"(dst), "l"(src), "r"(sz));
        }
        #pragma unroll
        for (int j = 0; j < 4; j++) {
            int idx = tid + j * 256;
            int r = idx >> 3;
            int c = (idx & 7) * 8;
            const __half* src = Bt + (size_t)(col0 + r) * K + tile * 64 + c;
            unsigned dst = sb + (A6_BUF + r * HSTR6 + c) * 2;
            asm volatile("cp.async.cg.shared.global [%0], [%1], 16, %2;"
                         :: "r"(dst), "l"(src), "r"(16));
        }
        asm volatile("cp.async.commit_group;");
    };

    issue(0, 0);
    if (KT > 1) issue(1, 1);

    #pragma unroll 1
    for (int kt = 0; kt < KT; kt++) {
        if (kt < KT - 1) asm volatile("cp.async.wait_group 1;");
        else             asm volatile("cp.async.wait_group 0;");
        __syncthreads();
        if (kt + 2 < KT) issue(kt + 2, (kt + 2) % 3);

        const unsigned st = smem_base + (kt % 3) * ST6_BUF * 2;
        #pragma unroll
        for (int k16 = 0; k16 < 4; k16++) {
            unsigned int af[4][4], bf[4][2];
            #pragma unroll
            for (int i = 0; i < 4; i++) {
                int rowA = wm * 64 + i * 16 + mr + ((mi & 1) << 3);
                int colA = k16 * 16 + ((mi >> 1) << 3);
                unsigned addr = st + (rowA * HSTR6 + colA) * 2;
                asm volatile(
                    "ldmatrix.sync.aligned.m8n8.x4.shared.b16 {%0,%1,%2,%3}, [%4];"
                    : "=r"(af[i][0]), "=r"(af[i][1]), "=r"(af[i][2]), "=r"(af[i][3])
                    : "r"(addr));
            }
            #pragma unroll
            for (int jp = 0; jp < 2; jp++) {
                int rowB = wn * 32 + jp * 16 + mr + ((mi >> 1) << 3);
                int colB = k16 * 16 + ((mi & 1) << 3);
                unsigned addr = st + (A6_BUF + rowB * HSTR6 + colB) * 2;
                asm volatile(
                    "ldmatrix.sync.aligned.m8n8.x4.shared.b16 {%0,%1,%2,%3}, [%4];"
                    : "=r"(bf[2 * jp][0]), "=r"(bf[2 * jp][1]),
                      "=r"(bf[2 * jp + 1][0]), "=r"(bf[2 * jp + 1][1])
                    : "r"(addr));
            }
            #pragma unroll
            for (int i = 0; i < 4; i++)
                #pragma unroll
                for (int jn = 0; jn < 4; jn++) {
                    asm volatile(
                        "mma.sync.aligned.m16n8k16.row.col.f32.f16.f16.f32 "
                        "{%0,%1,%2,%3}, {%4,%5,%6,%7}, {%8,%9}, {%0,%1,%2,%3};"
                        : "+f"(acc[i][jn][0]), "+f"(acc[i][jn][1]),
                          "+f"(acc[i][jn][2]), "+f"(acc[i][jn][3])
                        : "r"(af[i][0]), "r"(af[i][1]), "r"(af[i][2]), "r"(af[i][3]),
                          "r"(bf[jn][0]), "r"(bf[jn][1]));
                }
        }
    }

    #pragma unroll
    for (int i = 0; i < 4; i++) {
        #pragma unroll
        for (int jn = 0; jn < 4; jn++) {
            int row = row0 + wm * 64 + i * 16 + g;
            int col = col0 + wn * 32 + jn * 8 + tg * 2;
            float b0 = 0.f, b1 = 0.f;
            if (bp != nullptr) { b0 = bp[col]; b1 = bp[col + 1]; }
            if (row < M) {
                if (outh)
                    *(__half2*)((__half*)Cp + (size_t)row * CC + col) =
                        __floats2half2_rn(acc[i][jn][0] + b0, acc[i][jn][1] + b1);
                else
                    *(float2*)((float*)Cp + (size_t)row * CC + col) =
                        make_float2(acc[i][jn][0] + b0, acc[i][jn][1] + b1);
            }
            if (row + 8 < M) {
                if (outh)
                    *(__half2*)((__half*)Cp + (size_t)(row + 8) * CC + col) =
                        __floats2half2_rn(acc[i][jn][2] + b0, acc[i][jn][3] + b1);
                else
                    *(float2*)((float*)Cp + (size_t)(row + 8) * CC + col) =
                        make_float2(acc[i][jn][2] + b0, acc[i][jn][3] + b1);
            }
        }
    }
}

// ---------------- CORA prep ----------------
__global__ __launch_bounds__(256) void cora_prep(
    const float* __restrict__ target, const float* __restrict__ anchor,
    const float* __restrict__ pres,
    float* __restrict__ uhat, float* __restrict__ ahat, float* __restrict__ Gout)
{
    __shared__ float red[32];
    __shared__ float ud[CC], ad[CC];
    const int s = blockIdx.x, tid = threadIdx.x;
    const float* p0 = pres + (size_t)s * CC;
    const float* p1 = pres + (size_t)(SS + s) * CC;
    const float* tg = target + (size_t)s * CC;
    const float* an = anchor + (size_t)s * CC;

    float g00 = 0, g01 = 0, g11 = 0, bt0 = 0, bt1 = 0, ba0 = 0, ba1 = 0;
    for (int d = tid; d < CC; d += 256) {
        float a = p0[d], b = p1[d], t = tg[d], u = an[d];
        g00 += a * a; g01 += a * b; g11 += b * b;
        bt0 += a * t; bt1 += b * t;
        ba0 += a * u; ba1 += b * u;
    }
    g00 = blockSum(g00, red); g01 = blockSum(g01, red); g11 = blockSum(g11, red);
    bt0 = blockSum(bt0, red); bt1 = blockSum(bt1, red);
    ba0 = blockSum(ba0, red); ba1 = blockSum(ba1, red);

    float det = g00 * g11 - g01 * g01;
    float ct0 = (g11 * bt0 - g01 * bt1) / det, ct1 = (g00 * bt1 - g01 * bt0) / det;
    float ca0 = (g11 * ba0 - g01 * ba1) / det, ca1 = (g00 * ba1 - g01 * ba0) / det;

    float nu2 = 0;
    for (int d = tid; d < CC; d += 256) {
        float udv = tg[d] - (p0[d] * ct0 + p1[d] * ct1);
        float adv = an[d] - (p0[d] * ca0 + p1[d] * ca1);
        ud[d] = udv; ad[d] = adv;
        nu2 += udv * udv;
    }
    nu2 = blockSum(nu2, red);
    float nu = sqrtf(nu2) + EPSI;

    float dua = 0;
    for (int d = tid; d < CC; d += 256) {
        float uh = ud[d] / nu;
        ud[d] = uh;
        uhat[(size_t)s * CC + d] = uh;
        dua += uh * ad[d];
    }
    dua = blockSum(dua, red);

    float na2 = 0;
    for (int d = tid; d < CC; d += 256) {
        float at = ad[d] - dua * ud[d];
        ad[d] = at;
        na2 += at * at;
    }
    na2 = blockSum(na2, red);
    float na = sqrtf(na2) + EPSI;

    for (int d = tid; d < CC; d += 256)
        ahat[(size_t)s * CC + d] = ad[d] / na;

    if (tid == 0) { Gout[s * 3 + 0] = g00; Gout[s * 3 + 1] = g01; Gout[s * 3 + 2] = g11; }
}

// ---------------- CORA apply: writes erased V as fp16 transposed [b][d][s80] ----
__global__ __launch_bounds__(256) void cora_apply(
    const float* __restrict__ Vin, const float* __restrict__ pres,
    const float* __restrict__ G, const float* __restrict__ uhat,
    const float* __restrict__ ahat, __half* __restrict__ Vth)
{
    __shared__ float red[32];
    const int bs = blockIdx.x, s = bs % SS, b = bs / SS, tid = threadIdx.x;
    const float* v = Vin + (size_t)bs * CC;
    const float* p0 = pres + (size_t)s * CC;
    const float* p1 = pres + (size_t)(SS + s) * CC;
    const float* uh = uhat + (size_t)s * CC;
    const float* ah = ahat + (size_t)s * CC;

    float b0 = 0, b1 = 0;
    for (int d = tid; d < CC; d += 256) {
        float vd = v[d];
        b0 += p0[d] * vd; b1 += p1[d] * vd;
    }
    b0 = blockSum(b0, red); b1 = blockSum(b1, red);

    float g00 = G[s * 3], g01 = G[s * 3 + 1], g11 = G[s * 3 + 2];
    float det = g00 * g11 - g01 * g01;
    float c0 = (g11 * b0 - g01 * b1) / det;
    float c1 = (g00 * b1 - g01 * b0) / det;

    float nf2 = 0, t = 0;
    for (int d = tid; d < CC; d += 256) {
        float vp = p0[d] * c0 + p1[d] * c1;
        float vf = v[d] - vp;
        nf2 += vf * vf;
        t += uh[d] * vf;
    }
    nf2 = blockSum(nf2, red);
    t = blockSum(t, red);

    float denom = sqrtf(nf2) + EPSI;
    bool keep = (fabsf(t) / denom) < TAU;

    for (int d = tid; d < CC; d += 256) {
        float vp = p0[d] * c0 + p1[d] * c1;
        float vf = v[d] - vp;
        float vn = vp + vf - t * uh[d] + BETA * t * ah[d];
        float vo = keep ? v[d] : vn;
        Vth[((size_t)(b * CC + d)) * 80 + s] = __float2half_rn(vo);
    }
}

// =====================================================================
// Tensor-core attention: per (b, h, 128-row tile). V pre-transposed fp16.
// 2 CTAs/SM co-residency.
// =====================================================================
#define AQ_ROWS 128
#define ASTRH 88
#define ATTN2_SMEM ((AQ_ROWS * ASTRH + 80 * ASTRH + 80 * ASTRH) * 2)

__global__ __launch_bounds__(256, 2) void attn_tc(
    const __half* __restrict__ Q, const __half* __restrict__ Kp,
    const __half* __restrict__ Vth, __half* __restrict__ O)
{
    extern __shared__ __half ash[];
    __half* Qs = ash;
    __half* Ks = Qs + AQ_ROWS * ASTRH;
    __half* Vt = Ks + 80 * ASTRH;

    const int b = blockIdx.z, h = blockIdx.y;
    const int n0 = blockIdx.x * AQ_ROWS;
    const int tid = threadIdx.x;

    // zero K pad region only (rows 77..79 must be 0)
    {
        unsigned int* z = (unsigned int*)Ks;
        for (int i = tid; i < 80 * ASTRH / 2; i += 256) z[i] = 0u;
    }
    __syncthreads();

    for (int i = tid * 4; i < AQ_ROWS * DH; i += 1024) {
        int r = i / DH, d = i % DH;
        *(uint2*)&Qs[r * ASTRH + d] =
            *(const uint2*)(Q + ((size_t)(b * NN + n0 + r)) * CC + h * DH + d);
    }
    for (int i = tid * 4; i < SS * DH; i += 1024) {
        int r = i / DH, d = i % DH;
        *(uint2*)&Ks[r * ASTRH + d] =
            *(const uint2*)(Kp + ((size_t)(b * SS + r)) * CC + h * DH + d);
    }
    // V^T: coalesced fp16 loads; pad cols s=77..79 are zero in global (.bss)
    for (int i = tid * 4; i < DH * 80; i += 1024) {
        int d = i / 80, s = i % 80;
        *(uint2*)&Vt[d * ASTRH + s] =
            *(const uint2*)(Vth + ((size_t)(b * CC + h * DH + d)) * 80 + s);
    }
    __syncthreads();

    const int w = tid >> 5, lane = tid & 31;
    const int g = lane >> 2, tg = lane & 3;
    const int qrow = w * 16;

    float c[10][4];
    #pragma unroll
    for (int j = 0; j < 10; j++)
        #pragma unroll
        for (int e = 0; e < 4; e++) c[j][e] = 0.0f;

    const unsigned int* Qu = (const unsigned int*)Qs;
    const unsigned int* Ku = (const unsigned int*)Ks;
    #pragma unroll
    for (int kk = 0; kk < 5; kk++) {
        unsigned int a0, a1, a2, a3;
        const unsigned int* p = Qu + (qrow + g) * (ASTRH / 2) + kk * 8 + tg;
        a0 = p[0];
        a1 = p[8 * (ASTRH / 2)];
        a2 = p[4];
        a3 = p[8 * (ASTRH / 2) + 4];
        #pragma unroll
        for (int j = 0; j < 10; j++) {
            const unsigned int* q = Ku + (j * 8 + g) * (ASTRH / 2) + kk * 8 + tg;
            unsigned int b0 = q[0], b1 = q[4];
            asm volatile(
                "mma.sync.aligned.m16n8k16.row.col.f32.f16.f16.f32 "
                "{%0,%1,%2,%3}, {%4,%5,%6,%7}, {%8,%9}, {%0,%1,%2,%3};"
                : "+f"(c[j][0]), "+f"(c[j][1]), "+f"(c[j][2]), "+f"(c[j][3])
                : "r"(a0), "r"(a1), "r"(a2), "r"(a3), "r"(b0), "r"(b1));
        }
    }

    const float scale = 0.11180339887498948f;
    const float NEG = -1e30f;
    #pragma unroll
    for (int j = 0; j < 10; j++)
        #pragma unroll
        for (int e = 0; e < 4; e++) c[j][e] *= scale;
    if (tg == 2) { c[9][1] = NEG; c[9][3] = NEG; }
    if (tg == 3) { c[9][0] = NEG; c[9][1] = NEG; c[9][2] = NEG; c[9][3] = NEG; }

    float m0 = NEG, m1 = NEG;
    #pragma unroll
    for (int j = 0; j < 10; j++) {
        m0 = fmaxf(m0, fmaxf(c[j][0], c[j][1]));
        m1 = fmaxf(m1, fmaxf(c[j][2], c[j][3]));
    }
    m0 = fmaxf(m0, __shfl_xor_sync(0xffffffffu, m0, 1));
    m0 = fmaxf(m0, __shfl_xor_sync(0xffffffffu, m0, 2));
    m1 = fmaxf(m1, __shfl_xor_sync(0xffffffffu, m1, 1));
    m1 = fmaxf(m1, __shfl_xor_sync(0xffffffffu, m1, 2));

    float s0 = 0.f, s1 = 0.f;
    #pragma unroll
    for (int j = 0; j < 10; j++) {
        c[j][0] = expf(c[j][0] - m0);
        c[j][1] = expf(c[j][1] - m0);
        c[j][2] = expf(c[j][2] - m1);
        c[j][3] = expf(c[j][3] - m1);
        s0 += c[j][0] + c[j][1];
        s1 += c[j][2] + c[j][3];
    }
    s0 += __shfl_xor_sync(0xffffffffu, s0, 1);
    s0 += __shfl_xor_sync(0xffffffffu, s0, 2);
    s1 += __shfl_xor_sync(0xffffffffu, s1, 1);
    s1 += __shfl_xor_sync(0xffffffffu, s1, 2);
    const float i0 = 1.0f / s0, i1 = 1.0f / s1;
    #pragma unroll
    for (int j = 0; j < 10; j++) {
        c[j][0] *= i0; c[j][1] *= i0;
        c[j][2] *= i1; c[j][3] *= i1;
    }

    float o[10][4];
    #pragma unroll
    for (int j = 0; j < 10; j++)
        #pragma unroll
        for (int e = 0; e < 4; e++) o[j][e] = 0.0f;

    const unsigned int* Vu = (const unsigned int*)Vt;
    #pragma unroll
    for (int kk = 0; kk < 5; kk++) {
        __half2 ha0 = __floats2half2_rn(c[2 * kk][0],     c[2 * kk][1]);
        __half2 ha1 = __floats2half2_rn(c[2 * kk][2],     c[2 * kk][3]);
        __half2 ha2 = __floats2half2_rn(c[2 * kk + 1][0], c[2 * kk + 1][1]);
        __half2 ha3 = __floats2half2_rn(c[2 * kk + 1][2], c[2 * kk + 1][3]);
        unsigned int a0 = *(unsigned int*)&ha0;
        unsigned int a1 = *(unsigned int*)&ha1;
        unsigned int a2 = *(unsigned int*)&ha2;
        unsigned int a3 = *(unsigned int*)&ha3;
        #pragma unroll
        for (int jd = 0; jd < 10; jd++) {
            const unsigned int* q = Vu + (jd * 8 + g) * (ASTRH / 2) + kk * 8 + tg;
            unsigned int b0 = q[0], b1 = q[4];
            asm volatile(
                "mma.sync.aligned.m16n8k16.row.col.f32.f16.f16.f32 "
                "{%0,%1,%2,%3}, {%4,%5,%6,%7}, {%8,%9}, {%0,%1,%2,%3};"
                : "+f"(o[jd][0]), "+f"(o[jd][1]), "+f"(o[jd][2]), "+f"(o[jd][3])
                : "r"(a0), "r"(a1), "r"(a2), "r"(a3), "r"(b0), "r"(b1));
        }
    }

    const int r0 = n0 + qrow + g;
    #pragma unroll
    for (int jd = 0; jd < 10; jd++) {
        int col = h * DH + jd * 8 + tg * 2;
        *(__half2*)(O + ((size_t)(b * NN + r0)) * CC + col) =
            __floats2half2_rn(o[jd][0], o[jd][1]);
        *(__half2*)(O + ((size_t)(b * NN + r0 + 8)) * CC + col) =
            __floats2half2_rn(o[jd][2], o[jd][3]);
    }
}

// ---------------- launch ----------------
extern "C" void kernel_launch(void* const* d_in, const int* in_sizes, int n_in,
                              void* d_out, int out_size)
{
    static float *Vb = nullptr, *Uh = nullptr, *Ah = nullptr, *Gm = nullptr;
    static __half *Xh = nullptr, *Eh = nullptr, *Qh = nullptr, *Kh = nullptr,
                  *Vth = nullptr, *Attnh = nullptr, *Wh = nullptr;
    static cudaStream_t sSide = nullptr;
    static cudaEvent_t evFork = nullptr, evW = nullptr, evJoin = nullptr;
    static bool init = false;
    if (!init) {
        cudaGetSymbolAddress((void**)&Xh, g_Xh);
        cudaGetSymbolAddress((void**)&Eh, g_Eh);
        cudaGetSymbolAddress((void**)&Qh, g_Qh);
        cudaGetSymbolAddress((void**)&Attnh, g_attnh);
        cudaGetSymbolAddress((void**)&Kh, g_Kh);
        cudaGetSymbolAddress((void**)&Vb, g_V);
        cudaGetSymbolAddress((void**)&Vth, g_Vth);
        cudaGetSymbolAddress((void**)&Uh, g_uhat);
        cudaGetSymbolAddress((void**)&Ah, g_ahat);
        cudaGetSymbolAddress((void**)&Gm, g_G);
        cudaGetSymbolAddress((void**)&Wh, g_Wh);
        cudaFuncSetAttribute(attn_tc, cudaFuncAttributeMaxDynamicSharedMemorySize,
                             ATTN2_SMEM);
        cudaFuncSetAttribute(gemm_v6, cudaFuncAttributeMaxDynamicSharedMemorySize,
                             GV6_SMEM);
        cudaStreamCreateWithFlags(&sSide, cudaStreamNonBlocking);
        cudaEventCreateWithFlags(&evFork, cudaEventDisableTiming);
        cudaEventCreateWithFlags(&evW, cudaEventDisableTiming);
        cudaEventCreateWithFlags(&evJoin, cudaEventDisableTiming);
        init = true;
    }

    const float* X    = (const float*)d_in[0];
    const float* E    = (const float*)d_in[1];
    const float* Wq   = (const float*)d_in[2];
    const float* Wk   = (const float*)d_in[3];
    const float* Wv   = (const float*)d_in[4];
    const float* Wo   = (const float*)d_in[5];
    const float* bo   = (const float*)d_in[6];
    const float* tgt  = (const float*)d_in[7];
    const float* anc  = (const float*)d_in[8];
    const float* pres = (const float*)d_in[9];
    float* out = (float*)d_out;

    __half* WqT = Wh + 0 * (XD * CC);
    __half* WkT = Wh + 1 * (XD * CC);
    __half* WvT = Wh + 2 * (XD * CC);
    __half* WoT = Wh + 3 * (XD * CC);

    // ---- fork side stream ----
    cudaEventRecord(evFork, 0);
    cudaStreamWaitEvent(sSide, evFork, 0);

    // side chain: weights + E path + K/V proj + CORA (writes Vth fp16 transposed)
    transpose_all<<<dim3(CC / 32, XD / 32, 4), 256, 0, sSide>>>(Wq, Wk, Wv, Wo, Wh);
    cudaEventRecord(evW, sSide);   // WqT/WoT ready for main
    to_half8<<<((BB * SS * XD) / 8 + 255) / 256, 256, 0, sSide>>>(E, Eh, BB * SS * XD);
    gemm_v6<<<dim3(2 * (CC / 128), (BB * SS + 127) / 128), 256, GV6_SMEM, sSide>>>(
        Eh, WkT, nullptr, Kh, 1, WvT, Vb, 0, CC / 128, BB * SS, XD);
    cora_prep<<<SS, 256, 0, sSide>>>(tgt, anc, pres, Uh, Ah, Gm);
    cora_apply<<<BB * SS, 256, 0, sSide>>>(Vb, pres, Gm, Uh, Ah, Vth);
    cudaEventRecord(evJoin, sSide);

    // main chain: full X conversion + single Q proj
    to_half8<<<(BB * NN * CC) / 8 / 256, 256>>>(X, Xh, BB * NN * CC);
    cudaStreamWaitEvent(0, evW, 0);
    gemm_v6<<<dim3(CC / 128, (BB * NN) / 128), 256, GV6_SMEM>>>(
        Xh, WqT, nullptr, Qh, 1, nullptr, nullptr, 0, CC / 128, BB * NN, CC);

    // join: attention needs Kh + Vth
    cudaStreamWaitEvent(0, evJoin, 0);
    attn_tc<<<dim3(NN / AQ_ROWS, HH, BB), 256, ATTN2_SMEM>>>(Qh, Kh, Vth, Attnh);

    // output projection + bias (fp32 out)
    gemm_v6<<<dim3(CC / 128, (BB * NN) / 128), 256, GV6_SMEM>>>(
        Attnh, WoT, bo, out, 0, nullptr, nullptr, 0, CC / 128, BB * NN, CC);
}

// round 16
// speedup vs baseline: 1.0014x; 1.0014x over previous
#include <cuda_runtime.h>
#include <cuda_fp16.h>
#include <math.h>
#include <stdint.h>

// Problem constants
#define BB 8
#define NN 4096
#define CC 640
#define SS 77
#define XD 768
#define HH 8
#define DH 80
#define BETA 0.5f
#define TAU 0.1f
#define EPSI 1e-8f

// ---------------- scratch (no cudaMalloc allowed) ----------------
__device__ __half g_Xh[BB * NN * CC];      // X, fp16
__device__ __half g_Qh[BB * NN * CC];      // Q, fp16
__device__ __half g_attnh[BB * NN * CC];   // attention out, fp16
__device__ __half g_Eh[BB * SS * XD];      // E, fp16
__device__ __half g_Kh[BB * SS * CC];      // K, fp16
__device__ float g_V[BB * SS * CC];
__device__ __half g_Vth[BB * CC * 80];     // CORA-erased V, fp16, [b][d][s] (pads stay 0)
__device__ float g_uhat[SS * CC];
__device__ float g_ahat[SS * CC];
__device__ float g_G[SS * 3];
__device__ __half g_Wh[4][XD * CC];        // transposed fp16 weights [n][k]

// ---------------- block reduce helper ----------------
__device__ __forceinline__ float blockSum(float v, float* red) {
    #pragma unroll
    for (int o = 16; o; o >>= 1) v += __shfl_xor_sync(0xffffffffu, v, o);
    int w = threadIdx.x >> 5, l = threadIdx.x & 31;
    __syncthreads();
    if (l == 0) red[w] = v;
    __syncthreads();
    if (w == 0) {
        float x = (l < (int)(blockDim.x >> 5)) ? red[l] : 0.0f;
        #pragma unroll
        for (int o = 4; o; o >>= 1) x += __shfl_xor_sync(0xffffffffu, x, o);
        if (l == 0) red[0] = x;
    }
    __syncthreads();
    return red[0];
}

// ---------------- fp32 -> fp16 bulk convert (n % 8 == 0) ----------------
__global__ __launch_bounds__(256) void to_half8(
    const float* __restrict__ src, __half* __restrict__ dst, int n)
{
    int i = (blockIdx.x * 256 + threadIdx.x) * 8;
    if (i >= n) return;
    float4 a = *(const float4*)(src + i);
    float4 b = *(const float4*)(src + i + 4);
    __half2 h[4];
    h[0] = __floats2half2_rn(a.x, a.y);
    h[1] = __floats2half2_rn(a.z, a.w);
    h[2] = __floats2half2_rn(b.x, b.y);
    h[3] = __floats2half2_rn(b.z, b.w);
    *(uint4*)(dst + i) = *(uint4*)h;
}

// ---------------- fused weight transpose + fp16: Wh[z][n][k] ----------------
__global__ __launch_bounds__(256) void transpose_all(
    const float* __restrict__ Wq, const float* __restrict__ Wk,
    const float* __restrict__ Wv, const float* __restrict__ Wo,
    __half* __restrict__ Wh)
{
    __shared__ float t[32][33];
    const int z = blockIdx.z;
    const float* W = (z == 0) ? Wq : (z == 1) ? Wk : (z == 2) ? Wv : Wo;
    const int K = (z == 1 || z == 2) ? XD : CC;
    __half* Wt = Wh + (size_t)z * (XD * CC);

    const int k0 = blockIdx.y * 32, n0 = blockIdx.x * 32;
    if (k0 >= K) return;
    const int tx = threadIdx.x & 31, ty = threadIdx.x >> 5;
    #pragma unroll
    for (int i = ty; i < 32; i += 8) {
        int k = k0 + i, n = n0 + tx;
        if (k < K) t[i][tx] = W[(size_t)k * CC + n];
    }
    __syncthreads();
    #pragma unroll
    for (int i = ty; i < 32; i += 8) {
        int n = n0 + i, k = k0 + tx;
        if (k < K)
            Wt[(size_t)n * K + k] = __float2half_rn(t[tx][i]);
    }
}

// =====================================================================
// FP16 tensor-core GEMM v6 (proven R12): k64 stages, 3-stage cp.async,
// ldmatrix, 2 CTAs/SM, dual-B, runtime out dtype.
// =====================================================================
#define HSTR6 72
#define A6_BUF (128 * HSTR6)
#define B6_BUF (128 * HSTR6)
#define ST6_BUF (A6_BUF + B6_BUF)
#define GV6_SMEM (3 * ST6_BUF * 2)   // 110592 B

__global__ __launch_bounds__(256, 2) void gemm_v6(
    const __half* __restrict__ A,
    const __half* __restrict__ B1, const float* __restrict__ bias,
    void* __restrict__ C1, int outh1,
    const __half* __restrict__ B2, void* __restrict__ C2, int outh2,
    int nsplit, int M, int K)
{
    extern __shared__ __half sh[];
    const int tid = threadIdx.x;
    int bx = blockIdx.x;
    const __half* Bt = B1;
    void* Cp = C1;
    int outh = outh1;
    const float* bp = bias;
    if (B2 != nullptr && bx >= nsplit) { Bt = B2; Cp = C2; outh = outh2; bp = nullptr; bx -= nsplit; }

    const int wid = tid >> 5, lane = tid & 31;
    const int wm = wid >> 2, wn = wid & 3;
    const int g = lane >> 2, tg = lane & 3;
    const int row0 = blockIdx.y * 128, col0 = bx * 128;

    const unsigned smem_base = (unsigned)__cvta_generic_to_shared(sh);
    const int mi = lane >> 3;
    const int mr = lane & 7;

    float acc[4][4][4];
    #pragma unroll
    for (int i = 0; i < 4; i++)
        #pragma unroll
        for (int j = 0; j < 4; j++)
            #pragma unroll
            for (int r = 0; r < 4; r++) acc[i][j][r] = 0.0f;

    const int KT = K / 64;

    auto issue = [&](int tile, int stage) {
        const unsigned sb = smem_base + stage * ST6_BUF * 2;
        #pragma unroll
        for (int j = 0; j < 4; j++) {
            int idx = tid + j * 256;
            int r = idx >> 3;
            int c = (idx & 7) * 8;
            int gr = row0 + r;
            int sz = (gr < M) ? 16 : 0;
            const __half* src = A + (size_t)(gr < M ? gr : (M - 1)) * K + tile * 64 + c;
            unsigned dst = sb + (r * HSTR6 + c) * 2;
            asm volatile("cp.async.cg.shared.global [%0], [%1], 16, %2;"
                         :: "r"(dst), "l"(src), "r"(sz));
        }
        #pragma unroll
        for (int j = 0; j < 4; j++) {
            int idx = tid + j * 256;
            int r = idx >> 3;
            int c = (idx & 7) * 8;
            const __half* src = Bt + (size_t)(col0 + r) * K + tile * 64 + c;
            unsigned dst = sb + (A6_BUF + r * HSTR6 + c) * 2;
            asm volatile("cp.async.cg.shared.global [%0], [%1], 16, %2;"
                         :: "r"(dst), "l"(src), "r"(16));
        }
        asm volatile("cp.async.commit_group;");
    };

    issue(0, 0);
    if (KT > 1) issue(1, 1);

    #pragma unroll 1
    for (int kt = 0; kt < KT; kt++) {
        if (kt < KT - 1) asm volatile("cp.async.wait_group 1;");
        else             asm volatile("cp.async.wait_group 0;");
        __syncthreads();
        if (kt + 2 < KT) issue(kt + 2, (kt + 2) % 3);

        const unsigned st = smem_base + (kt % 3) * ST6_BUF * 2;
        #pragma unroll
        for (int k16 = 0; k16 < 4; k16++) {
            unsigned int af[4][4], bf[4][2];
            #pragma unroll
            for (int i = 0; i < 4; i++) {
                int rowA = wm * 64 + i * 16 + mr + ((mi & 1) << 3);
                int colA = k16 * 16 + ((mi >> 1) << 3);
                unsigned addr = st + (rowA * HSTR6 + colA) * 2;
                asm volatile(
                    "ldmatrix.sync.aligned.m8n8.x4.shared.b16 {%0,%1,%2,%3}, [%4];"
                    : "=r"(af[i][0]), "=r"(af[i][1]), "=r"(af[i][2]), "=r"(af[i][3])
                    : "r"(addr));
            }
            #pragma unroll
            for (int jp = 0; jp < 2; jp++) {
                int rowB = wn * 32 + jp * 16 + mr + ((mi >> 1) << 3);
                int colB = k16 * 16 + ((mi & 1) << 3);
                unsigned addr = st + (A6_BUF + rowB * HSTR6 + colB) * 2;
                asm volatile(
                    "ldmatrix.sync.aligned.m8n8.x4.shared.b16 {%0,%1,%2,%3}, [%4];"
                    : "=r"(bf[2 * jp][0]), "=r"(bf[2 * jp][1]),
                      "=r"(bf[2 * jp + 1][0]), "=r"(bf[2 * jp + 1][1])
                    : "r"(addr));
            }
            #pragma unroll
            for (int i = 0; i < 4; i++)
                #pragma unroll
                for (int jn = 0; jn < 4; jn++) {
                    asm volatile(
                        "mma.sync.aligned.m16n8k16.row.col.f32.f16.f16.f32 "
                        "{%0,%1,%2,%3}, {%4,%5,%6,%7}, {%8,%9}, {%0,%1,%2,%3};"
                        : "+f"(acc[i][jn][0]), "+f"(acc[i][jn][1]),
                          "+f"(acc[i][jn][2]), "+f"(acc[i][jn][3])
                        : "r"(af[i][0]), "r"(af[i][1]), "r"(af[i][2]), "r"(af[i][3]),
                          "r"(bf[jn][0]), "r"(bf[jn][1]));
                }
        }
    }

    #pragma unroll
    for (int i = 0; i < 4; i++) {
        #pragma unroll
        for (int jn = 0; jn < 4; jn++) {
            int row = row0 + wm * 64 + i * 16 + g;
            int col = col0 + wn * 32 + jn * 8 + tg * 2;
            float b0 = 0.f, b1 = 0.f;
            if (bp != nullptr) { b0 = bp[col]; b1 = bp[col + 1]; }
            if (row < M) {
                if (outh)
                    *(__half2*)((__half*)Cp + (size_t)row * CC + col) =
                        __floats2half2_rn(acc[i][jn][0] + b0, acc[i][jn][1] + b1);
                else
                    *(float2*)((float*)Cp + (size_t)row * CC + col) =
                        make_float2(acc[i][jn][0] + b0, acc[i][jn][1] + b1);
            }
            if (row + 8 < M) {
                if (outh)
                    *(__half2*)((__half*)Cp + (size_t)(row + 8) * CC + col) =
                        __floats2half2_rn(acc[i][jn][2] + b0, acc[i][jn][3] + b1);
                else
                    *(float2*)((float*)Cp + (size_t)(row + 8) * CC + col) =
                        make_float2(acc[i][jn][2] + b0, acc[i][jn][3] + b1);
            }
        }
    }
}

// ---------------- CORA prep ----------------
__global__ __launch_bounds__(256) void cora_prep(
    const float* __restrict__ target, const float* __restrict__ anchor,
    const float* __restrict__ pres,
    float* __restrict__ uhat, float* __restrict__ ahat, float* __restrict__ Gout)
{
    __shared__ float red[32];
    __shared__ float ud[CC], ad[CC];
    const int s = blockIdx.x, tid = threadIdx.x;
    const float* p0 = pres + (size_t)s * CC;
    const float* p1 = pres + (size_t)(SS + s) * CC;
    const float* tg = target + (size_t)s * CC;
    const float* an = anchor + (size_t)s * CC;

    float g00 = 0, g01 = 0, g11 = 0, bt0 = 0, bt1 = 0, ba0 = 0, ba1 = 0;
    for (int d = tid; d < CC; d += 256) {
        float a = p0[d], b = p1[d], t = tg[d], u = an[d];
        g00 += a * a; g01 += a * b; g11 += b * b;
        bt0 += a * t; bt1 += b * t;
        ba0 += a * u; ba1 += b * u;
    }
    g00 = blockSum(g00, red); g01 = blockSum(g01, red); g11 = blockSum(g11, red);
    bt0 = blockSum(bt0, red); bt1 = blockSum(bt1, red);
    ba0 = blockSum(ba0, red); ba1 = blockSum(ba1, red);

    float det = g00 * g11 - g01 * g01;
    float ct0 = (g11 * bt0 - g01 * bt1) / det, ct1 = (g00 * bt1 - g01 * bt0) / det;
    float ca0 = (g11 * ba0 - g01 * ba1) / det, ca1 = (g00 * ba1 - g01 * ba0) / det;

    float nu2 = 0;
    for (int d = tid; d < CC; d += 256) {
        float udv = tg[d] - (p0[d] * ct0 + p1[d] * ct1);
        float adv = an[d] - (p0[d] * ca0 + p1[d] * ca1);
        ud[d] = udv; ad[d] = adv;
        nu2 += udv * udv;
    }
    nu2 = blockSum(nu2, red);
    float nu = sqrtf(nu2) + EPSI;

    float dua = 0;
    for (int d = tid; d < CC; d += 256) {
        float uh = ud[d] / nu;
        ud[d] = uh;
        uhat[(size_t)s * CC + d] = uh;
        dua += uh * ad[d];
    }
    dua = blockSum(dua, red);

    float na2 = 0;
    for (int d = tid; d < CC; d += 256) {
        float at = ad[d] - dua * ud[d];
        ad[d] = at;
        na2 += at * at;
    }
    na2 = blockSum(na2, red);
    float na = sqrtf(na2) + EPSI;

    for (int d = tid; d < CC; d += 256)
        ahat[(size_t)s * CC + d] = ad[d] / na;

    if (tid == 0) { Gout[s * 3 + 0] = g00; Gout[s * 3 + 1] = g01; Gout[s * 3 + 2] = g11; }
}

// ---------------- CORA apply: writes erased V as fp16 transposed [b][d][s80] ----
__global__ __launch_bounds__(256) void cora_apply(
    const float* __restrict__ Vin, const float* __restrict__ pres,
    const float* __restrict__ G, const float* __restrict__ uhat,
    const float* __restrict__ ahat, __half* __restrict__ Vth)
{
    __shared__ float red[32];
    const int bs = blockIdx.x, s = bs % SS, b = bs / SS, tid = threadIdx.x;
    const float* v = Vin + (size_t)bs * CC;
    const float* p0 = pres + (size_t)s * CC;
    const float* p1 = pres + (size_t)(SS + s) * CC;
    const float* uh = uhat + (size_t)s * CC;
    const float* ah = ahat + (size_t)s * CC;

    float b0 = 0, b1 = 0;
    for (int d = tid; d < CC; d += 256) {
        float vd = v[d];
        b0 += p0[d] * vd; b1 += p1[d] * vd;
    }
    b0 = blockSum(b0, red); b1 = blockSum(b1, red);

    float g00 = G[s * 3], g01 = G[s * 3 + 1], g11 = G[s * 3 + 2];
    float det = g00 * g11 - g01 * g01;
    float c0 = (g11 * b0 - g01 * b1) / det;
    float c1 = (g00 * b1 - g01 * b0) / det;

    float nf2 = 0, t = 0;
    for (int d = tid; d < CC; d += 256) {
        float vp = p0[d] * c0 + p1[d] * c1;
        float vf = v[d] - vp;
        nf2 += vf * vf;
        t += uh[d] * vf;
    }
    nf2 = blockSum(nf2, red);
    t = blockSum(t, red);

    float denom = sqrtf(nf2) + EPSI;
    bool keep = (fabsf(t) / denom) < TAU;

    for (int d = tid; d < CC; d += 256) {
        float vp = p0[d] * c0 + p1[d] * c1;
        float vf = v[d] - vp;
        float vn = vp + vf - t * uh[d] + BETA * t * ah[d];
        float vo = keep ? v[d] : vn;
        Vth[((size_t)(b * CC + d)) * 80 + s] = __float2half_rn(vo);
    }
}

// =====================================================================
// Tensor-core attention: per (b, h, 128-row tile). V pre-transposed fp16.
// 2 CTAs/SM; P converted to fp16 frags BEFORE PV so c[] dies early
// (keeps regs < 128, no spill).
// =====================================================================
#define AQ_ROWS 128
#define ASTRH 88
#define ATTN2_SMEM ((AQ_ROWS * ASTRH + 80 * ASTRH + 80 * ASTRH) * 2)

__global__ __launch_bounds__(256, 2) void attn_tc(
    const __half* __restrict__ Q, const __half* __restrict__ Kp,
    const __half* __restrict__ Vth, __half* __restrict__ O)
{
    extern __shared__ __half ash[];
    __half* Qs = ash;
    __half* Ks = Qs + AQ_ROWS * ASTRH;
    __half* Vt = Ks + 80 * ASTRH;

    const int b = blockIdx.z, h = blockIdx.y;
    const int n0 = blockIdx.x * AQ_ROWS;
    const int tid = threadIdx.x;

    // zero K pad region only (rows 77..79 must be 0)
    {
        unsigned int* z = (unsigned int*)Ks;
        for (int i = tid; i < 80 * ASTRH / 2; i += 256) z[i] = 0u;
    }
    __syncthreads();

    for (int i = tid * 4; i < AQ_ROWS * DH; i += 1024) {
        int r = i / DH, d = i % DH;
        *(uint2*)&Qs[r * ASTRH + d] =
            *(const uint2*)(Q + ((size_t)(b * NN + n0 + r)) * CC + h * DH + d);
    }
    for (int i = tid * 4; i < SS * DH; i += 1024) {
        int r = i / DH, d = i % DH;
        *(uint2*)&Ks[r * ASTRH + d] =
            *(const uint2*)(Kp + ((size_t)(b * SS + r)) * CC + h * DH + d);
    }
    // V^T: coalesced fp16 loads; pad cols s=77..79 are zero in global (.bss)
    for (int i = tid * 4; i < DH * 80; i += 1024) {
        int d = i / 80, s = i % 80;
        *(uint2*)&Vt[d * ASTRH + s] =
            *(const uint2*)(Vth + ((size_t)(b * CC + h * DH + d)) * 80 + s);
    }
    __syncthreads();

    const int w = tid >> 5, lane = tid & 31;
    const int g = lane >> 2, tg = lane & 3;
    const int qrow = w * 16;

    // pa: packed fp16 P fragments (filled after softmax; c dies before PV)
    unsigned int pa[5][4];

    {
        float c[10][4];
        #pragma unroll
        for (int j = 0; j < 10; j++)
            #pragma unroll
            for (int e = 0; e < 4; e++) c[j][e] = 0.0f;

        const unsigned int* Qu = (const unsigned int*)Qs;
        const unsigned int* Ku = (const unsigned int*)Ks;
        #pragma unroll
        for (int kk = 0; kk < 5; kk++) {
            unsigned int a0, a1, a2, a3;
            const unsigned int* p = Qu + (qrow + g) * (ASTRH / 2) + kk * 8 + tg;
            a0 = p[0];
            a1 = p[8 * (ASTRH / 2)];
            a2 = p[4];
            a3 = p[8 * (ASTRH / 2) + 4];
            #pragma unroll
            for (int j = 0; j < 10; j++) {
                const unsigned int* q = Ku + (j * 8 + g) * (ASTRH / 2) + kk * 8 + tg;
                unsigned int b0 = q[0], b1 = q[4];
                asm volatile(
                    "mma.sync.aligned.m16n8k16.row.col.f32.f16.f16.f32 "
                    "{%0,%1,%2,%3}, {%4,%5,%6,%7}, {%8,%9}, {%0,%1,%2,%3};"
                    : "+f"(c[j][0]), "+f"(c[j][1]), "+f"(c[j][2]), "+f"(c[j][3])
                    : "r"(a0), "r"(a1), "r"(a2), "r"(a3), "r"(b0), "r"(b1));
            }
        }

        const float scale = 0.11180339887498948f;
        const float NEG = -1e30f;
        #pragma unroll
        for (int j = 0; j < 10; j++)
            #pragma unroll
            for (int e = 0; e < 4; e++) c[j][e] *= scale;
        if (tg == 2) { c[9][1] = NEG; c[9][3] = NEG; }
        if (tg == 3) { c[9][0] = NEG; c[9][1] = NEG; c[9][2] = NEG; c[9][3] = NEG; }

        float m0 = NEG, m1 = NEG;
        #pragma unroll
        for (int j = 0; j < 10; j++) {
            m0 = fmaxf(m0, fmaxf(c[j][0], c[j][1]));
            m1 = fmaxf(m1, fmaxf(c[j][2], c[j][3]));
        }
        m0 = fmaxf(m0, __shfl_xor_sync(0xffffffffu, m0, 1));
        m0 = fmaxf(m0, __shfl_xor_sync(0xffffffffu, m0, 2));
        m1 = fmaxf(m1, __shfl_xor_sync(0xffffffffu, m1, 1));
        m1 = fmaxf(m1, __shfl_xor_sync(0xffffffffu, m1, 2));

        float s0 = 0.f, s1 = 0.f;
        #pragma unroll
        for (int j = 0; j < 10; j++) {
            c[j][0] = expf(c[j][0] - m0);
            c[j][1] = expf(c[j][1] - m0);
            c[j][2] = expf(c[j][2] - m1);
            c[j][3] = expf(c[j][3] - m1);
            s0 += c[j][0] + c[j][1];
            s1 += c[j][2] + c[j][3];
        }
        s0 += __shfl_xor_sync(0xffffffffu, s0, 1);
        s0 += __shfl_xor_sync(0xffffffffu, s0, 2);
        s1 += __shfl_xor_sync(0xffffffffu, s1, 1);
        s1 += __shfl_xor_sync(0xffffffffu, s1, 2);
        const float i0 = 1.0f / s0, i1 = 1.0f / s1;

        // normalize + pack to fp16 fragments; c dead after this loop
        #pragma unroll
        for (int kk = 0; kk < 5; kk++) {
            __half2 h0 = __floats2half2_rn(c[2 * kk][0] * i0,     c[2 * kk][1] * i0);
            __half2 h1 = __floats2half2_rn(c[2 * kk][2] * i1,     c[2 * kk][3] * i1);
            __half2 h2 = __floats2half2_rn(c[2 * kk + 1][0] * i0, c[2 * kk + 1][1] * i0);
            __half2 h3 = __floats2half2_rn(c[2 * kk + 1][2] * i1, c[2 * kk + 1][3] * i1);
            pa[kk][0] = *(unsigned int*)&h0;
            pa[kk][1] = *(unsigned int*)&h1;
            pa[kk][2] = *(unsigned int*)&h2;
            pa[kk][3] = *(unsigned int*)&h3;
        }
    }

    // ---- PV ----
    float o[10][4];
    #pragma unroll
    for (int j = 0; j < 10; j++)
        #pragma unroll
        for (int e = 0; e < 4; e++) o[j][e] = 0.0f;

    const unsigned int* Vu = (const unsigned int*)Vt;
    #pragma unroll
    for (int kk = 0; kk < 5; kk++) {
        #pragma unroll
        for (int jd = 0; jd < 10; jd++) {
            const unsigned int* q = Vu + (jd * 8 + g) * (ASTRH / 2) + kk * 8 + tg;
            unsigned int b0 = q[0], b1 = q[4];
            asm volatile(
                "mma.sync.aligned.m16n8k16.row.col.f32.f16.f16.f32 "
                "{%0,%1,%2,%3}, {%4,%5,%6,%7}, {%8,%9}, {%0,%1,%2,%3};"
                : "+f"(o[jd][0]), "+f"(o[jd][1]), "+f"(o[jd][2]), "+f"(o[jd][3])
                : "r"(pa[kk][0]), "r"(pa[kk][1]), "r"(pa[kk][2]), "r"(pa[kk][3]),
                  "r"(b0), "r"(b1));
        }
    }

    const int r0 = n0 + qrow + g;
    #pragma unroll
    for (int jd = 0; jd < 10; jd++) {
        int col = h * DH + jd * 8 + tg * 2;
        *(__half2*)(O + ((size_t)(b * NN + r0)) * CC + col) =
            __floats2half2_rn(o[jd][0], o[jd][1]);
        *(__half2*)(O + ((size_t)(b * NN + r0 + 8)) * CC + col) =
            __floats2half2_rn(o[jd][2], o[jd][3]);
    }
}

// ---------------- launch ----------------
extern "C" void kernel_launch(void* const* d_in, const int* in_sizes, int n_in,
                              void* d_out, int out_size)
{
    static float *Vb = nullptr, *Uh = nullptr, *Ah = nullptr, *Gm = nullptr;
    static __half *Xh = nullptr, *Eh = nullptr, *Qh = nullptr, *Kh = nullptr,
                  *Vth = nullptr, *Attnh = nullptr, *Wh = nullptr;
    static cudaStream_t sSide = nullptr;
    static cudaEvent_t evFork = nullptr, evW = nullptr, evJoin = nullptr;
    static bool init = false;
    if (!init) {
        cudaGetSymbolAddress((void**)&Xh, g_Xh);
        cudaGetSymbolAddress((void**)&Eh, g_Eh);
        cudaGetSymbolAddress((void**)&Qh, g_Qh);
        cudaGetSymbolAddress((void**)&Attnh, g_attnh);
        cudaGetSymbolAddress((void**)&Kh, g_Kh);
        cudaGetSymbolAddress((void**)&Vb, g_V);
        cudaGetSymbolAddress((void**)&Vth, g_Vth);
        cudaGetSymbolAddress((void**)&Uh, g_uhat);
        cudaGetSymbolAddress((void**)&Ah, g_ahat);
        cudaGetSymbolAddress((void**)&Gm, g_G);
        cudaGetSymbolAddress((void**)&Wh, g_Wh);
        cudaFuncSetAttribute(attn_tc, cudaFuncAttributeMaxDynamicSharedMemorySize,
                             ATTN2_SMEM);
        cudaFuncSetAttribute(gemm_v6, cudaFuncAttributeMaxDynamicSharedMemorySize,
                             GV6_SMEM);
        cudaStreamCreateWithFlags(&sSide, cudaStreamNonBlocking);
        cudaEventCreateWithFlags(&evFork, cudaEventDisableTiming);
        cudaEventCreateWithFlags(&evW, cudaEventDisableTiming);
        cudaEventCreateWithFlags(&evJoin, cudaEventDisableTiming);
        init = true;
    }

    const float* X    = (const float*)d_in[0];
    const float* E    = (const float*)d_in[1];
    const float* Wq   = (const float*)d_in[2];
    const float* Wk   = (const float*)d_in[3];
    const float* Wv   = (const float*)d_in[4];
    const float* Wo   = (const float*)d_in[5];
    const float* bo   = (const float*)d_in[6];
    const float* tgt  = (const float*)d_in[7];
    const float* anc  = (const float*)d_in[8];
    const float* pres = (const float*)d_in[9];
    float* out = (float*)d_out;

    __half* WqT = Wh + 0 * (XD * CC);
    __half* WkT = Wh + 1 * (XD * CC);
    __half* WvT = Wh + 2 * (XD * CC);
    __half* WoT = Wh + 3 * (XD * CC);

    // ---- fork side stream ----
    cudaEventRecord(evFork, 0);
    cudaStreamWaitEvent(sSide, evFork, 0);

    // side chain: weights + E path + K/V proj + CORA (writes Vth fp16 transposed)
    transpose_all<<<dim3(CC / 32, XD / 32, 4), 256, 0, sSide>>>(Wq, Wk, Wv, Wo, Wh);
    cudaEventRecord(evW, sSide);   // WqT/WoT ready for main
    to_half8<<<((BB * SS * XD) / 8 + 255) / 256, 256, 0, sSide>>>(E, Eh, BB * SS * XD);
    gemm_v6<<<dim3(2 * (CC / 128), (BB * SS + 127) / 128), 256, GV6_SMEM, sSide>>>(
        Eh, WkT, nullptr, Kh, 1, WvT, Vb, 0, CC / 128, BB * SS, XD);
    cora_prep<<<SS, 256, 0, sSide>>>(tgt, anc, pres, Uh, Ah, Gm);
    cora_apply<<<BB * SS, 256, 0, sSide>>>(Vb, pres, Gm, Uh, Ah, Vth);
    cudaEventRecord(evJoin, sSide);

    // main chain: full X conversion + single Q proj
    to_half8<<<(BB * NN * CC) / 8 / 256, 256>>>(X, Xh, BB * NN * CC);
    cudaStreamWaitEvent(0, evW, 0);
    gemm_v6<<<dim3(CC / 128, (BB * NN) / 128), 256, GV6_SMEM>>>(
        Xh, WqT, nullptr, Qh, 1, nullptr, nullptr, 0, CC / 128, BB * NN, CC);

    // join: attention needs Kh + Vth
    cudaStreamWaitEvent(0, evJoin, 0);
    attn_tc<<<dim3(NN / AQ_ROWS, HH, BB), 256, ATTN2_SMEM>>>(Qh, Kh, Vth, Attnh);

    // output projection + bias (fp32 out)
    gemm_v6<<<dim3(CC / 128, (BB * NN) / 128), 256, GV6_SMEM>>>(
        Attnh, WoT, bo, out, 0, nullptr, nullptr, 0, CC / 128, BB * NN, CC);
}

// round 17
// speedup vs baseline: 1.0603x; 1.0588x over previous
#include <cuda_runtime.h>
#include <cuda_fp16.h>
#include <math.h>
#include <stdint.h>

// Problem constants
#define BB 8
#define NN 4096
#define CC 640
#define SS 77
#define XD 768
#define HH 8
#define DH 80
#define BETA 0.5f
#define TAU 0.1f
#define EPSI 1e-8f

// ---------------- scratch (no cudaMalloc allowed) ----------------
__device__ __half g_Xh[BB * NN * CC];      // X, fp16
__device__ __half g_Qh[BB * NN * CC];      // Q, fp16
__device__ __half g_attnh[BB * NN * CC];   // attention out, fp16
__device__ __half g_Eh[BB * SS * XD];      // E, fp16
__device__ __half g_Kh[BB * SS * CC];      // K, fp16
__device__ float g_V[BB * SS * CC];
__device__ __half g_Vth[BB * CC * 80];     // CORA-erased V, fp16, [b][d][s] (pads stay 0)
__device__ float g_uhat[SS * CC];
__device__ float g_ahat[SS * CC];
__device__ float g_G[SS * 3];
__device__ __half g_Wh[4][XD * CC];        // transposed fp16 weights [n][k]

// ---------------- block reduce helper ----------------
__device__ __forceinline__ float blockSum(float v, float* red) {
    #pragma unroll
    for (int o = 16; o; o >>= 1) v += __shfl_xor_sync(0xffffffffu, v, o);
    int w = threadIdx.x >> 5, l = threadIdx.x & 31;
    __syncthreads();
    if (l == 0) red[w] = v;
    __syncthreads();
    if (w == 0) {
        float x = (l < (int)(blockDim.x >> 5)) ? red[l] : 0.0f;
        #pragma unroll
        for (int o = 4; o; o >>= 1) x += __shfl_xor_sync(0xffffffffu, x, o);
        if (l == 0) red[0] = x;
    }
    __syncthreads();
    return red[0];
}

// ---------------- fp32 -> fp16 bulk convert (n % 8 == 0) ----------------
__global__ __launch_bounds__(256) void to_half8(
    const float* __restrict__ src, __half* __restrict__ dst, int n)
{
    int i = (blockIdx.x * 256 + threadIdx.x) * 8;
    if (i >= n) return;
    float4 a = *(const float4*)(src + i);
    float4 b = *(const float4*)(src + i + 4);
    __half2 h[4];
    h[0] = __floats2half2_rn(a.x, a.y);
    h[1] = __floats2half2_rn(a.z, a.w);
    h[2] = __floats2half2_rn(b.x, b.y);
    h[3] = __floats2half2_rn(b.z, b.w);
    *(uint4*)(dst + i) = *(uint4*)h;
}

// ---------------- fused weight transpose + fp16: Wh[z][n][k] ----------------
__global__ __launch_bounds__(256) void transpose_all(
    const float* __restrict__ Wq, const float* __restrict__ Wk,
    const float* __restrict__ Wv, const float* __restrict__ Wo,
    __half* __restrict__ Wh)
{
    __shared__ float t[32][33];
    const int z = blockIdx.z;
    const float* W = (z == 0) ? Wq : (z == 1) ? Wk : (z == 2) ? Wv : Wo;
    const int K = (z == 1 || z == 2) ? XD : CC;
    __half* Wt = Wh + (size_t)z * (XD * CC);

    const int k0 = blockIdx.y * 32, n0 = blockIdx.x * 32;
    if (k0 >= K) return;
    const int tx = threadIdx.x & 31, ty = threadIdx.x >> 5;
    #pragma unroll
    for (int i = ty; i < 32; i += 8) {
        int k = k0 + i, n = n0 + tx;
        if (k < K) t[i][tx] = W[(size_t)k * CC + n];
    }
    __syncthreads();
    #pragma unroll
    for (int i = ty; i < 32; i += 8) {
        int n = n0 + i, k = k0 + tx;
        if (k < K)
            Wt[(size_t)n * K + k] = __float2half_rn(t[tx][i]);
    }
}

// =====================================================================
// FP16 tensor-core GEMM v6 (proven R12): k64 stages, 3-stage cp.async,
// ldmatrix, 2 CTAs/SM, dual-B, runtime out dtype.
// =====================================================================
#define HSTR6 72
#define A6_BUF (128 * HSTR6)
#define B6_BUF (128 * HSTR6)
#define ST6_BUF (A6_BUF + B6_BUF)
#define GV6_SMEM (3 * ST6_BUF * 2)   // 110592 B

__global__ __launch_bounds__(256, 2) void gemm_v6(
    const __half* __restrict__ A,
    const __half* __restrict__ B1, const float* __restrict__ bias,
    void* __restrict__ C1, int outh1,
    const __half* __restrict__ B2, void* __restrict__ C2, int outh2,
    int nsplit, int M, int K)
{
    extern __shared__ __half sh[];
    const int tid = threadIdx.x;
    int bx = blockIdx.x;
    const __half* Bt = B1;
    void* Cp = C1;
    int outh = outh1;
    const float* bp = bias;
    if (B2 != nullptr && bx >= nsplit) { Bt = B2; Cp = C2; outh = outh2; bp = nullptr; bx -= nsplit; }

    const int wid = tid >> 5, lane = tid & 31;
    const int wm = wid >> 2, wn = wid & 3;
    const int g = lane >> 2, tg = lane & 3;
    const int row0 = blockIdx.y * 128, col0 = bx * 128;

    const unsigned smem_base = (unsigned)__cvta_generic_to_shared(sh);
    const int mi = lane >> 3;
    const int mr = lane & 7;

    float acc[4][4][4];
    #pragma unroll
    for (int i = 0; i < 4; i++)
        #pragma unroll
        for (int j = 0; j < 4; j++)
            #pragma unroll
            for (int r = 0; r < 4; r++) acc[i][j][r] = 0.0f;

    const int KT = K / 64;

    auto issue = [&](int tile, int stage) {
        const unsigned sb = smem_base + stage * ST6_BUF * 2;
        #pragma unroll
        for (int j = 0; j < 4; j++) {
            int idx = tid + j * 256;
            int r = idx >> 3;
            int c = (idx & 7) * 8;
            int gr = row0 + r;
            int sz = (gr < M) ? 16 : 0;
            const __half* src = A + (size_t)(gr < M ? gr : (M - 1)) * K + tile * 64 + c;
            unsigned dst = sb + (r * HSTR6 + c) * 2;
            asm volatile("cp.async.cg.shared.global [%0], [%1], 16, %2;"
                         :: "r"(dst), "l"(src), "r"(sz));
        }
        #pragma unroll
        for (int j = 0; j < 4; j++) {
            int idx = tid + j * 256;
            int r = idx >> 3;
            int c = (idx & 7) * 8;
            const __half* src = Bt + (size_t)(col0 + r) * K + tile * 64 + c;
            unsigned dst = sb + (A6_BUF + r * HSTR6 + c) * 2;
            asm volatile("cp.async.cg.shared.global [%0], [%1], 16, %2;"
                         :: "r"(dst), "l"(src), "r"(16));
        }
        asm volatile("cp.async.commit_group;");
    };

    issue(0, 0);
    if (KT > 1) issue(1, 1);

    #pragma unroll 1
    for (int kt = 0; kt < KT; kt++) {
        if (kt < KT - 1) asm volatile("cp.async.wait_group 1;");
        else             asm volatile("cp.async.wait_group 0;");
        __syncthreads();
        if (kt + 2 < KT) issue(kt + 2, (kt + 2) % 3);

        const unsigned st = smem_base + (kt % 3) * ST6_BUF * 2;
        #pragma unroll
        for (int k16 = 0; k16 < 4; k16++) {
            unsigned int af[4][4], bf[4][2];
            #pragma unroll
            for (int i = 0; i < 4; i++) {
                int rowA = wm * 64 + i * 16 + mr + ((mi & 1) << 3);
                int colA = k16 * 16 + ((mi >> 1) << 3);
                unsigned addr = st + (rowA * HSTR6 + colA) * 2;
                asm volatile(
                    "ldmatrix.sync.aligned.m8n8.x4.shared.b16 {%0,%1,%2,%3}, [%4];"
                    : "=r"(af[i][0]), "=r"(af[i][1]), "=r"(af[i][2]), "=r"(af[i][3])
                    : "r"(addr));
            }
            #pragma unroll
            for (int jp = 0; jp < 2; jp++) {
                int rowB = wn * 32 + jp * 16 + mr + ((mi >> 1) << 3);
                int colB = k16 * 16 + ((mi & 1) << 3);
                unsigned addr = st + (A6_BUF + rowB * HSTR6 + colB) * 2;
                asm volatile(
                    "ldmatrix.sync.aligned.m8n8.x4.shared.b16 {%0,%1,%2,%3}, [%4];"
                    : "=r"(bf[2 * jp][0]), "=r"(bf[2 * jp][1]),
                      "=r"(bf[2 * jp + 1][0]), "=r"(bf[2 * jp + 1][1])
                    : "r"(addr));
            }
            #pragma unroll
            for (int i = 0; i < 4; i++)
                #pragma unroll
                for (int jn = 0; jn < 4; jn++) {
                    asm volatile(
                        "mma.sync.aligned.m16n8k16.row.col.f32.f16.f16.f32 "
                        "{%0,%1,%2,%3}, {%4,%5,%6,%7}, {%8,%9}, {%0,%1,%2,%3};"
                        : "+f"(acc[i][jn][0]), "+f"(acc[i][jn][1]),
                          "+f"(acc[i][jn][2]), "+f"(acc[i][jn][3])
                        : "r"(af[i][0]), "r"(af[i][1]), "r"(af[i][2]), "r"(af[i][3]),
                          "r"(bf[jn][0]), "r"(bf[jn][1]));
                }
        }
    }

    #pragma unroll
    for (int i = 0; i < 4; i++) {
        #pragma unroll
        for (int jn = 0; jn < 4; jn++) {
            int row = row0 + wm * 64 + i * 16 + g;
            int col = col0 + wn * 32 + jn * 8 + tg * 2;
            float b0 = 0.f, b1 = 0.f;
            if (bp != nullptr) { b0 = bp[col]; b1 = bp[col + 1]; }
            if (row < M) {
                if (outh)
                    *(__half2*)((__half*)Cp + (size_t)row * CC + col) =
                        __floats2half2_rn(acc[i][jn][0] + b0, acc[i][jn][1] + b1);
                else
                    *(float2*)((float*)Cp + (size_t)row * CC + col) =
                        make_float2(acc[i][jn][0] + b0, acc[i][jn][1] + b1);
            }
            if (row + 8 < M) {
                if (outh)
                    *(__half2*)((__half*)Cp + (size_t)(row + 8) * CC + col) =
                        __floats2half2_rn(acc[i][jn][2] + b0, acc[i][jn][3] + b1);
                else
                    *(float2*)((float*)Cp + (size_t)(row + 8) * CC + col) =
                        make_float2(acc[i][jn][2] + b0, acc[i][jn][3] + b1);
            }
        }
    }
}

// ---------------- CORA prep ----------------
__global__ __launch_bounds__(256) void cora_prep(
    const float* __restrict__ target, const float* __restrict__ anchor,
    const float* __restrict__ pres,
    float* __restrict__ uhat, float* __restrict__ ahat, float* __restrict__ Gout)
{
    __shared__ float red[32];
    __shared__ float ud[CC], ad[CC];
    const int s = blockIdx.x, tid = threadIdx.x;
    const float* p0 = pres + (size_t)s * CC;
    const float* p1 = pres + (size_t)(SS + s) * CC;
    const float* tg = target + (size_t)s * CC;
    const float* an = anchor + (size_t)s * CC;

    float g00 = 0, g01 = 0, g11 = 0, bt0 = 0, bt1 = 0, ba0 = 0, ba1 = 0;
    for (int d = tid; d < CC; d += 256) {
        float a = p0[d], b = p1[d], t = tg[d], u = an[d];
        g00 += a * a; g01 += a * b; g11 += b * b;
        bt0 += a * t; bt1 += b * t;
        ba0 += a * u; ba1 += b * u;
    }
    g00 = blockSum(g00, red); g01 = blockSum(g01, red); g11 = blockSum(g11, red);
    bt0 = blockSum(bt0, red); bt1 = blockSum(bt1, red);
    ba0 = blockSum(ba0, red); ba1 = blockSum(ba1, red);

    float det = g00 * g11 - g01 * g01;
    float ct0 = (g11 * bt0 - g01 * bt1) / det, ct1 = (g00 * bt1 - g01 * bt0) / det;
    float ca0 = (g11 * ba0 - g01 * ba1) / det, ca1 = (g00 * ba1 - g01 * ba0) / det;

    float nu2 = 0;
    for (int d = tid; d < CC; d += 256) {
        float udv = tg[d] - (p0[d] * ct0 + p1[d] * ct1);
        float adv = an[d] - (p0[d] * ca0 + p1[d] * ca1);
        ud[d] = udv; ad[d] = adv;
        nu2 += udv * udv;
    }
    nu2 = blockSum(nu2, red);
    float nu = sqrtf(nu2) + EPSI;

    float dua = 0;
    for (int d = tid; d < CC; d += 256) {
        float uh = ud[d] / nu;
        ud[d] = uh;
        uhat[(size_t)s * CC + d] = uh;
        dua += uh * ad[d];
    }
    dua = blockSum(dua, red);

    float na2 = 0;
    for (int d = tid; d < CC; d += 256) {
        float at = ad[d] - dua * ud[d];
        ad[d] = at;
        na2 += at * at;
    }
    na2 = blockSum(na2, red);
    float na = sqrtf(na2) + EPSI;

    for (int d = tid; d < CC; d += 256)
        ahat[(size_t)s * CC + d] = ad[d] / na;

    if (tid == 0) { Gout[s * 3 + 0] = g00; Gout[s * 3 + 1] = g01; Gout[s * 3 + 2] = g11; }
}

// ---------------- CORA apply: writes erased V as fp16 transposed [b][d][s80] ----
__global__ __launch_bounds__(256) void cora_apply(
    const float* __restrict__ Vin, const float* __restrict__ pres,
    const float* __restrict__ G, const float* __restrict__ uhat,
    const float* __restrict__ ahat, __half* __restrict__ Vth)
{
    __shared__ float red[32];
    const int bs = blockIdx.x, s = bs % SS, b = bs / SS, tid = threadIdx.x;
    const float* v = Vin + (size_t)bs * CC;
    const float* p0 = pres + (size_t)s * CC;
    const float* p1 = pres + (size_t)(SS + s) * CC;
    const float* uh = uhat + (size_t)s * CC;
    const float* ah = ahat + (size_t)s * CC;

    float b0 = 0, b1 = 0;
    for (int d = tid; d < CC; d += 256) {
        float vd = v[d];
        b0 += p0[d] * vd; b1 += p1[d] * vd;
    }
    b0 = blockSum(b0, red); b1 = blockSum(b1, red);

    float g00 = G[s * 3], g01 = G[s * 3 + 1], g11 = G[s * 3 + 2];
    float det = g00 * g11 - g01 * g01;
    float c0 = (g11 * b0 - g01 * b1) / det;
    float c1 = (g00 * b1 - g01 * b0) / det;

    float nf2 = 0, t = 0;
    for (int d = tid; d < CC; d += 256) {
        float vp = p0[d] * c0 + p1[d] * c1;
        float vf = v[d] - vp;
        nf2 += vf * vf;
        t += uh[d] * vf;
    }
    nf2 = blockSum(nf2, red);
    t = blockSum(t, red);

    float denom = sqrtf(nf2) + EPSI;
    bool keep = (fabsf(t) / denom) < TAU;

    for (int d = tid; d < CC; d += 256) {
        float vp = p0[d] * c0 + p1[d] * c1;
        float vf = v[d] - vp;
        float vn = vp + vf - t * uh[d] + BETA * t * ah[d];
        float vo = keep ? v[d] : vn;
        Vth[((size_t)(b * CC + d)) * 80 + s] = __float2half_rn(vo);
    }
}

// =====================================================================
// Tensor-core attention: per (b, h, 128-row tile). V pre-transposed fp16.
// 1 CTA/SM (2 CTAs/SM measured 18us WORSE — R15/R16).
// =====================================================================
#define AQ_ROWS 128
#define ASTRH 88
#define ATTN2_SMEM ((AQ_ROWS * ASTRH + 80 * ASTRH + 80 * ASTRH) * 2)

__global__ __launch_bounds__(256) void attn_tc(
    const __half* __restrict__ Q, const __half* __restrict__ Kp,
    const __half* __restrict__ Vth, __half* __restrict__ O)
{
    extern __shared__ __half ash[];
    __half* Qs = ash;
    __half* Ks = Qs + AQ_ROWS * ASTRH;
    __half* Vt = Ks + 80 * ASTRH;

    const int b = blockIdx.z, h = blockIdx.y;
    const int n0 = blockIdx.x * AQ_ROWS;
    const int tid = threadIdx.x;

    // zero K pad region only (rows 77..79 must be 0)
    {
        unsigned int* z = (unsigned int*)Ks;
        for (int i = tid; i < 80 * ASTRH / 2; i += 256) z[i] = 0u;
    }
    __syncthreads();

    for (int i = tid * 4; i < AQ_ROWS * DH; i += 1024) {
        int r = i / DH, d = i % DH;
        *(uint2*)&Qs[r * ASTRH + d] =
            *(const uint2*)(Q + ((size_t)(b * NN + n0 + r)) * CC + h * DH + d);
    }
    for (int i = tid * 4; i < SS * DH; i += 1024) {
        int r = i / DH, d = i % DH;
        *(uint2*)&Ks[r * ASTRH + d] =
            *(const uint2*)(Kp + ((size_t)(b * SS + r)) * CC + h * DH + d);
    }
    // V^T: coalesced fp16 loads; pad cols s=77..79 are zero in global (.bss)
    for (int i = tid * 4; i < DH * 80; i += 1024) {
        int d = i / 80, s = i % 80;
        *(uint2*)&Vt[d * ASTRH + s] =
            *(const uint2*)(Vth + ((size_t)(b * CC + h * DH + d)) * 80 + s);
    }
    __syncthreads();

    const int w = tid >> 5, lane = tid & 31;
    const int g = lane >> 2, tg = lane & 3;
    const int qrow = w * 16;

    // pa: packed fp16 P fragments (filled after softmax; c dies before PV)
    unsigned int pa[5][4];

    {
        float c[10][4];
        #pragma unroll
        for (int j = 0; j < 10; j++)
            #pragma unroll
            for (int e = 0; e < 4; e++) c[j][e] = 0.0f;

        const unsigned int* Qu = (const unsigned int*)Qs;
        const unsigned int* Ku = (const unsigned int*)Ks;
        #pragma unroll
        for (int kk = 0; kk < 5; kk++) {
            unsigned int a0, a1, a2, a3;
            const unsigned int* p = Qu + (qrow + g) * (ASTRH / 2) + kk * 8 + tg;
            a0 = p[0];
            a1 = p[8 * (ASTRH / 2)];
            a2 = p[4];
            a3 = p[8 * (ASTRH / 2) + 4];
            #pragma unroll
            for (int j = 0; j < 10; j++) {
                const unsigned int* q = Ku + (j * 8 + g) * (ASTRH / 2) + kk * 8 + tg;
                unsigned int b0 = q[0], b1 = q[4];
                asm volatile(
                    "mma.sync.aligned.m16n8k16.row.col.f32.f16.f16.f32 "
                    "{%0,%1,%2,%3}, {%4,%5,%6,%7}, {%8,%9}, {%0,%1,%2,%3};"
                    : "+f"(c[j][0]), "+f"(c[j][1]), "+f"(c[j][2]), "+f"(c[j][3])
                    : "r"(a0), "r"(a1), "r"(a2), "r"(a3), "r"(b0), "r"(b1));
            }
        }

        const float scale = 0.11180339887498948f;
        const float NEG = -1e30f;
        #pragma unroll
        for (int j = 0; j < 10; j++)
            #pragma unroll
            for (int e = 0; e < 4; e++) c[j][e] *= scale;
        if (tg == 2) { c[9][1] = NEG; c[9][3] = NEG; }
        if (tg == 3) { c[9][0] = NEG; c[9][1] = NEG; c[9][2] = NEG; c[9][3] = NEG; }

        float m0 = NEG, m1 = NEG;
        #pragma unroll
        for (int j = 0; j < 10; j++) {
            m0 = fmaxf(m0, fmaxf(c[j][0], c[j][1]));
            m1 = fmaxf(m1, fmaxf(c[j][2], c[j][3]));
        }
        m0 = fmaxf(m0, __shfl_xor_sync(0xffffffffu, m0, 1));
        m0 = fmaxf(m0, __shfl_xor_sync(0xffffffffu, m0, 2));
        m1 = fmaxf(m1, __shfl_xor_sync(0xffffffffu, m1, 1));
        m1 = fmaxf(m1, __shfl_xor_sync(0xffffffffu, m1, 2));

        float s0 = 0.f, s1 = 0.f;
        #pragma unroll
        for (int j = 0; j < 10; j++) {
            c[j][0] = expf(c[j][0] - m0);
            c[j][1] = expf(c[j][1] - m0);
            c[j][2] = expf(c[j][2] - m1);
            c[j][3] = expf(c[j][3] - m1);
            s0 += c[j][0] + c[j][1];
            s1 += c[j][2] + c[j][3];
        }
        s0 += __shfl_xor_sync(0xffffffffu, s0, 1);
        s0 += __shfl_xor_sync(0xffffffffu, s0, 2);
        s1 += __shfl_xor_sync(0xffffffffu, s1, 1);
        s1 += __shfl_xor_sync(0xffffffffu, s1, 2);
        const float i0 = 1.0f / s0, i1 = 1.0f / s1;

        // normalize + pack to fp16 fragments; c dead after this loop
        #pragma unroll
        for (int kk = 0; kk < 5; kk++) {
            __half2 h0 = __floats2half2_rn(c[2 * kk][0] * i0,     c[2 * kk][1] * i0);
            __half2 h1 = __floats2half2_rn(c[2 * kk][2] * i1,     c[2 * kk][3] * i1);
            __half2 h2 = __floats2half2_rn(c[2 * kk + 1][0] * i0, c[2 * kk + 1][1] * i0);
            __half2 h3 = __floats2half2_rn(c[2 * kk + 1][2] * i1, c[2 * kk + 1][3] * i1);
            pa[kk][0] = *(unsigned int*)&h0;
            pa[kk][1] = *(unsigned int*)&h1;
            pa[kk][2] = *(unsigned int*)&h2;
            pa[kk][3] = *(unsigned int*)&h3;
        }
    }

    // ---- PV ----
    float o[10][4];
    #pragma unroll
    for (int j = 0; j < 10; j++)
        #pragma unroll
        for (int e = 0; e < 4; e++) o[j][e] = 0.0f;

    const unsigned int* Vu = (const unsigned int*)Vt;
    #pragma unroll
    for (int kk = 0; kk < 5; kk++) {
        #pragma unroll
        for (int jd = 0; jd < 10; jd++) {
            const unsigned int* q = Vu + (jd * 8 + g) * (ASTRH / 2) + kk * 8 + tg;
            unsigned int b0 = q[0], b1 = q[4];
            asm volatile(
                "mma.sync.aligned.m16n8k16.row.col.f32.f16.f16.f32 "
                "{%0,%1,%2,%3}, {%4,%5,%6,%7}, {%8,%9}, {%0,%1,%2,%3};"
                : "+f"(o[jd][0]), "+f"(o[jd][1]), "+f"(o[jd][2]), "+f"(o[jd][3])
                : "r"(pa[kk][0]), "r"(pa[kk][1]), "r"(pa[kk][2]), "r"(pa[kk][3]),
                  "r"(b0), "r"(b1));
        }
    }

    const int r0 = n0 + qrow + g;
    #pragma unroll
    for (int jd = 0; jd < 10; jd++) {
        int col = h * DH + jd * 8 + tg * 2;
        *(__half2*)(O + ((size_t)(b * NN + r0)) * CC + col) =
            __floats2half2_rn(o[jd][0], o[jd][1]);
        *(__half2*)(O + ((size_t)(b * NN + r0 + 8)) * CC + col) =
            __floats2half2_rn(o[jd][2], o[jd][3]);
    }
}

// ---------------- launch ----------------
extern "C" void kernel_launch(void* const* d_in, const int* in_sizes, int n_in,
                              void* d_out, int out_size)
{
    static float *Vb = nullptr, *Uh = nullptr, *Ah = nullptr, *Gm = nullptr;
    static __half *Xh = nullptr, *Eh = nullptr, *Qh = nullptr, *Kh = nullptr,
                  *Vth = nullptr, *Attnh = nullptr, *Wh = nullptr;
    static cudaStream_t sSide = nullptr;
    static cudaEvent_t evFork = nullptr, evW = nullptr, evJoin = nullptr;
    static bool init = false;
    if (!init) {
        cudaGetSymbolAddress((void**)&Xh, g_Xh);
        cudaGetSymbolAddress((void**)&Eh, g_Eh);
        cudaGetSymbolAddress((void**)&Qh, g_Qh);
        cudaGetSymbolAddress((void**)&Attnh, g_attnh);
        cudaGetSymbolAddress((void**)&Kh, g_Kh);
        cudaGetSymbolAddress((void**)&Vb, g_V);
        cudaGetSymbolAddress((void**)&Vth, g_Vth);
        cudaGetSymbolAddress((void**)&Uh, g_uhat);
        cudaGetSymbolAddress((void**)&Ah, g_ahat);
        cudaGetSymbolAddress((void**)&Gm, g_G);
        cudaGetSymbolAddress((void**)&Wh, g_Wh);
        cudaFuncSetAttribute(attn_tc, cudaFuncAttributeMaxDynamicSharedMemorySize,
                             ATTN2_SMEM);
        cudaFuncSetAttribute(gemm_v6, cudaFuncAttributeMaxDynamicSharedMemorySize,
                             GV6_SMEM);
        cudaStreamCreateWithFlags(&sSide, cudaStreamNonBlocking);
        cudaEventCreateWithFlags(&evFork, cudaEventDisableTiming);
        cudaEventCreateWithFlags(&evW, cudaEventDisableTiming);
        cudaEventCreateWithFlags(&evJoin, cudaEventDisableTiming);
        init = true;
    }

    const float* X    = (const float*)d_in[0];
    const float* E    = (const float*)d_in[1];
    const float* Wq   = (const float*)d_in[2];
    const float* Wk   = (const float*)d_in[3];
    const float* Wv   = (const float*)d_in[4];
    const float* Wo   = (const float*)d_in[5];
    const float* bo   = (const float*)d_in[6];
    const float* tgt  = (const float*)d_in[7];
    const float* anc  = (const float*)d_in[8];
    const float* pres = (const float*)d_in[9];
    float* out = (float*)d_out;

    __half* WqT = Wh + 0 * (XD * CC);
    __half* WkT = Wh + 1 * (XD * CC);
    __half* WvT = Wh + 2 * (XD * CC);
    __half* WoT = Wh + 3 * (XD * CC);

    // ---- fork side stream ----
    cudaEventRecord(evFork, 0);
    cudaStreamWaitEvent(sSide, evFork, 0);

    // side chain: weights + E path + K/V proj + CORA (writes Vth fp16 transposed)
    transpose_all<<<dim3(CC / 32, XD / 32, 4), 256, 0, sSide>>>(Wq, Wk, Wv, Wo, Wh);
    cudaEventRecord(evW, sSide);   // WqT/WoT ready for main
    to_half8<<<((BB * SS * XD) / 8 + 255) / 256, 256, 0, sSide>>>(E, Eh, BB * SS * XD);
    gemm_v6<<<dim3(2 * (CC / 128), (BB * SS + 127) / 128), 256, GV6_SMEM, sSide>>>(
        Eh, WkT, nullptr, Kh, 1, WvT, Vb, 0, CC / 128, BB * SS, XD);
    cora_prep<<<SS, 256, 0, sSide>>>(tgt, anc, pres, Uh, Ah, Gm);
    cora_apply<<<BB * SS, 256, 0, sSide>>>(Vb, pres, Gm, Uh, Ah, Vth);
    cudaEventRecord(evJoin, sSide);

    // main chain: full X conversion + single Q proj
    to_half8<<<(BB * NN * CC) / 8 / 256, 256>>>(X, Xh, BB * NN * CC);
    cudaStreamWaitEvent(0, evW, 0);
    gemm_v6<<<dim3(CC / 128, (BB * NN) / 128), 256, GV6_SMEM>>>(
        Xh, WqT, nullptr, Qh, 1, nullptr, nullptr, 0, CC / 128, BB * NN, CC);

    // join: attention needs Kh + Vth
    cudaStreamWaitEvent(0, evJoin, 0);
    attn_tc<<<dim3(NN / AQ_ROWS, HH, BB), 256, ATTN2_SMEM>>>(Qh, Kh, Vth, Attnh);

    // output projection + bias (fp32 out)
    gemm_v6<<<dim3(CC / 128, (BB * NN) / 128), 256, GV6_SMEM>>>(
        Attnh, WoT, bo, out, 0, nullptr, nullptr, 0, CC / 128, BB * NN, CC);
}